// round 1
// baseline (speedup 1.0000x reference)
#include <cuda_runtime.h>
#include <cstdint>

// LocalSelfAttention: bs=4, h=12, s=4096, d=64, block=64
// 3072 independent blocks; per block: S = Q K^T (64x64x64), softmax(+mask), O = P V.
// tf32 mma.sync with 3x-split (QK^T) and 2x-split (PV) for fp32-grade accuracy.

#define STR 68          // padded smem row stride in floats (conflict-free fragment loads)
#define SM_BYTES 70144  // 17408 (Qf/P) + 34816 (Khl) + 17408 (Vf) + 512 (kb/qm)

__device__ __forceinline__ uint32_t f2tf(float f) {
    uint32_t u;
    asm("cvt.rna.tf32.f32 %0, %1;" : "=r"(u) : "f"(f));
    return u;
}

__device__ __forceinline__ void mma8(float* d,
                                     uint32_t a0, uint32_t a1, uint32_t a2, uint32_t a3,
                                     uint32_t b0, uint32_t b1) {
    asm volatile(
        "mma.sync.aligned.m16n8k8.row.col.f32.tf32.tf32.f32 "
        "{%0,%1,%2,%3}, {%4,%5,%6,%7}, {%8,%9}, {%0,%1,%2,%3};"
        : "+f"(d[0]), "+f"(d[1]), "+f"(d[2]), "+f"(d[3])
        : "r"(a0), "r"(a1), "r"(a2), "r"(a3), "r"(b0), "r"(b1));
}

__global__ __launch_bounds__(128) void lsa_kernel(
    const float* __restrict__ Qg_, const float* __restrict__ Kg_,
    const float* __restrict__ Vg_, const float* __restrict__ Mg_,
    float* __restrict__ Og_)
{
    extern __shared__ float sm[];
    float*  Qf  = sm;                         // 64*STR floats; reused for P after S-gemm
    float2* Khl = (float2*)(sm + 64 * STR);   // 64*STR float2 (hi,lo interleaved)
    float*  Vf  = sm + 3 * 64 * STR;          // 64*STR floats (tf32-rounded)
    float*  kb  = Vf + 64 * STR;              // key-side additive bias (64)
    float*  qm  = kb + 64;                    // query-side mask values (64)

    const int tid = threadIdx.x;
    const int blk = blockIdx.x;
    const size_t base = (size_t)blk * 4096;   // tile is 4096 contiguous floats
    const int b  = blk / 768;                 // 768 = 12 heads * 64 blocks
    const int nb = blk & 63;

    // ---- Stage tiles to smem (fully coalesced float4; hi/lo split of K, rna-round V) ----
    const float4* Qg = (const float4*)(Qg_ + base);
    const float4* Kg = (const float4*)(Kg_ + base);
    const float4* Vg = (const float4*)(Vg_ + base);
    #pragma unroll
    for (int it = 0; it < 8; it++) {
        int i = tid + it * 128;          // 0..1023 float4s
        float4 q = Qg[i];
        float4 k = Kg[i];
        float4 v = Vg[i];
        int r = i >> 4;                  // row 0..63
        int c = (i & 15) << 2;           // col 0..60 step 4
        *(float4*)&Qf[r * STR + c] = q;
        float kk[4] = {k.x, k.y, k.z, k.w};
        float2* kp = &Khl[r * STR + c];
        #pragma unroll
        for (int j = 0; j < 4; j++) {
            float hi = __uint_as_float(f2tf(kk[j]));
            float lo = __uint_as_float(f2tf(kk[j] - hi));
            kp[j] = make_float2(hi, lo);
        }
        float4 vr;
        vr.x = __uint_as_float(f2tf(v.x));
        vr.y = __uint_as_float(f2tf(v.y));
        vr.z = __uint_as_float(f2tf(v.z));
        vr.w = __uint_as_float(f2tf(v.w));
        *(float4*)&Vf[r * STR + c] = vr;
    }
    if (tid < 64) {
        float m = Mg_[(size_t)b * 4096 + nb * 64 + tid];
        kb[tid] = (m == 0.0f) ? -10000.0f : 0.0f;
        qm[tid] = m;
    }
    __syncthreads();

    const int w    = tid >> 5;
    const int lane = tid & 31;
    const int g    = lane >> 2;   // group id (row within fragment)
    const int t    = lane & 3;    // thread-in-group (col within fragment)
    const int mb   = w * 16;      // warp's m-strip base row

    float acc[8][4];
    #pragma unroll
    for (int nt = 0; nt < 8; nt++) {
        acc[nt][0] = 0.f; acc[nt][1] = 0.f; acc[nt][2] = 0.f; acc[nt][3] = 0.f;
    }

    // ---- S = Q K^T, 3xTF32 (hi*hi + hi*lo + lo*hi) ----
    {
        const float* q0 = &Qf[(mb + g) * STR];
        const float* q1 = &Qf[(mb + g + 8) * STR];
        #pragma unroll
        for (int kt = 0; kt < 8; kt++) {
            int c0 = kt * 8 + t;
            int c1 = c0 + 4;
            float f00 = q0[c0], f10 = q1[c0], f01 = q0[c1], f11 = q1[c1];
            uint32_t a0h = f2tf(f00), a1h = f2tf(f10), a2h = f2tf(f01), a3h = f2tf(f11);
            uint32_t a0l = f2tf(f00 - __uint_as_float(a0h));
            uint32_t a1l = f2tf(f10 - __uint_as_float(a1h));
            uint32_t a2l = f2tf(f01 - __uint_as_float(a2h));
            uint32_t a3l = f2tf(f11 - __uint_as_float(a3h));
            #pragma unroll
            for (int nt = 0; nt < 8; nt++) {
                float2 bv0 = Khl[(nt * 8 + g) * STR + c0];
                float2 bv1 = Khl[(nt * 8 + g) * STR + c1];
                uint32_t b0h = __float_as_uint(bv0.x), b0l = __float_as_uint(bv0.y);
                uint32_t b1h = __float_as_uint(bv1.x), b1l = __float_as_uint(bv1.y);
                mma8(acc[nt], a0h, a1h, a2h, a3h, b0h, b1h);
                mma8(acc[nt], a0h, a1h, a2h, a3h, b0l, b1l);
                mma8(acc[nt], a0l, a1l, a2l, a3l, b0h, b1h);
            }
        }
    }

    // ---- softmax over 64 keys (rows split across quads; shuffle-reduce) ----
    float m0 = -3.0e38f, m1 = -3.0e38f;
    #pragma unroll
    for (int nt = 0; nt < 8; nt++) {
        float2 kbv = *(const float2*)&kb[nt * 8 + 2 * t];
        acc[nt][0] += kbv.x; acc[nt][1] += kbv.y;
        acc[nt][2] += kbv.x; acc[nt][3] += kbv.y;
        m0 = fmaxf(m0, fmaxf(acc[nt][0], acc[nt][1]));
        m1 = fmaxf(m1, fmaxf(acc[nt][2], acc[nt][3]));
    }
    m0 = fmaxf(m0, __shfl_xor_sync(0xffffffffu, m0, 1));
    m0 = fmaxf(m0, __shfl_xor_sync(0xffffffffu, m0, 2));
    m1 = fmaxf(m1, __shfl_xor_sync(0xffffffffu, m1, 1));
    m1 = fmaxf(m1, __shfl_xor_sync(0xffffffffu, m1, 2));
    float s0 = 0.f, s1 = 0.f;
    #pragma unroll
    for (int nt = 0; nt < 8; nt++) {
        acc[nt][0] = __expf(acc[nt][0] - m0);
        acc[nt][1] = __expf(acc[nt][1] - m0);
        acc[nt][2] = __expf(acc[nt][2] - m1);
        acc[nt][3] = __expf(acc[nt][3] - m1);
        s0 += acc[nt][0] + acc[nt][1];
        s1 += acc[nt][2] + acc[nt][3];
    }
    s0 += __shfl_xor_sync(0xffffffffu, s0, 1);
    s0 += __shfl_xor_sync(0xffffffffu, s0, 2);
    s1 += __shfl_xor_sync(0xffffffffu, s1, 1);
    s1 += __shfl_xor_sync(0xffffffffu, s1, 2);
    float r0 = (qm[mb + g]     == 0.0f) ? 0.0f : (1.0f / s0);
    float r1 = (qm[mb + g + 8] == 0.0f) ? 0.0f : (1.0f / s1);

    __syncthreads();   // all warps done reading Qf -> safe to overwrite with P

    #pragma unroll
    for (int nt = 0; nt < 8; nt++) {
        *(float2*)&Qf[(mb + g)     * STR + nt * 8 + 2 * t] =
            make_float2(acc[nt][0] * r0, acc[nt][1] * r0);
        *(float2*)&Qf[(mb + g + 8) * STR + nt * 8 + 2 * t] =
            make_float2(acc[nt][2] * r1, acc[nt][3] * r1);
    }
    __syncthreads();

    // ---- O = P V, 2xTF32 (P split hi/lo, V pre-rounded) ----
    #pragma unroll
    for (int nt = 0; nt < 8; nt++) {
        acc[nt][0] = 0.f; acc[nt][1] = 0.f; acc[nt][2] = 0.f; acc[nt][3] = 0.f;
    }
    {
        const float* p0 = &Qf[(mb + g) * STR];
        const float* p1 = &Qf[(mb + g + 8) * STR];
        #pragma unroll
        for (int kt = 0; kt < 8; kt++) {
            int c0 = kt * 8 + t;
            int c1 = c0 + 4;
            float f00 = p0[c0], f10 = p1[c0], f01 = p0[c1], f11 = p1[c1];
            uint32_t a0h = f2tf(f00), a1h = f2tf(f10), a2h = f2tf(f01), a3h = f2tf(f11);
            uint32_t a0l = f2tf(f00 - __uint_as_float(a0h));
            uint32_t a1l = f2tf(f10 - __uint_as_float(a1h));
            uint32_t a2l = f2tf(f01 - __uint_as_float(a2h));
            uint32_t a3l = f2tf(f11 - __uint_as_float(a3h));
            const float* v0 = &Vf[(kt * 8 + t)     * STR];
            const float* v1 = &Vf[(kt * 8 + t + 4) * STR];
            #pragma unroll
            for (int nt = 0; nt < 8; nt++) {
                uint32_t b0 = __float_as_uint(v0[nt * 8 + g]);
                uint32_t b1 = __float_as_uint(v1[nt * 8 + g]);
                mma8(acc[nt], a0h, a1h, a2h, a3h, b0, b1);
                mma8(acc[nt], a0l, a1l, a2l, a3l, b0, b1);
            }
        }
    }

    // ---- store O (float2, 32B-sector friendly) ----
    float* Og = Og_ + base;
    #pragma unroll
    for (int nt = 0; nt < 8; nt++) {
        *(float2*)&Og[(mb + g)     * 64 + nt * 8 + 2 * t] = make_float2(acc[nt][0], acc[nt][1]);
        *(float2*)&Og[(mb + g + 8) * 64 + nt * 8 + 2 * t] = make_float2(acc[nt][2], acc[nt][3]);
    }
}

extern "C" void kernel_launch(void* const* d_in, const int* in_sizes, int n_in,
                              void* d_out, int out_size) {
    const float* Q = (const float*)d_in[0];
    const float* K = (const float*)d_in[1];
    const float* V = (const float*)d_in[2];
    const float* M = (const float*)d_in[3];
    float* O = (float*)d_out;
    // Idempotent, not a stream op -> graph-capture safe; called every time (no static guards).
    cudaFuncSetAttribute(lsa_kernel, cudaFuncAttributeMaxDynamicSharedMemorySize, SM_BYTES);
    lsa_kernel<<<3072, 128, SM_BYTES>>>(Q, K, V, M, O);
}